// round 13
// baseline (speedup 1.0000x reference)
#include <cuda_runtime.h>
#include <math.h>

#define B_    2
#define CIN   32
#define COUT  32
#define D_    40
#define E_    3
#define SP    (D_*D_*D_)          // 64000
#define YTOT  (B_*COUT*SP)        // 4,096,000
#define OCG   4
#define NOCG  (COUT/OCG)          // 8
#define ZT    2
#define YT    8
#define SROW  48
#define NROWS ((ZT+2)*(YT+2))     // 40 rows
#define SLABVOL (NROWS*SROW)      // 1920 floats
#define UBLK  (CIN*3*16*OCG)      // 6144 floats per (b,ocg) of transformed U
#define NTHR  160

// ---- scratch (device globals; no runtime allocation) ----
__device__ float g_u[B_*NOCG*UBLK];     // [b][ocg][ic][dz][pos16][oc4]
__device__ float g_bias[B_*COUT];
__device__ float g_y[YTOT];
__device__ float g_sum[COUT];
__device__ float g_sumsq[COUT];
__device__ float g_scale[COUT];
__device__ float g_shift[COUT];

// ---------------------------------------------------------------------------
// Kernel 1: routing + Winograd-transformed weights U = G g G^T per (oc,ic,dz)
// ---------------------------------------------------------------------------
__global__ void k_route(const float* __restrict__ emb,
                        const float* __restrict__ rw,
                        const float* __restrict__ rb,
                        const float* __restrict__ ek,
                        const float* __restrict__ eb) {
    float r[B_][E_];
    #pragma unroll
    for (int b = 0; b < B_; b++)
        #pragma unroll
        for (int e = 0; e < E_; e++) {
            float t = fmaf(emb[b], rw[e], rb[e]);
            r[b][e] = 1.0f / (1.0f + expf(-t));
        }

    int idx = blockIdx.x * blockDim.x + threadIdx.x;
    const int TOT = B_ * NOCG * CIN * 3 * OCG;   // 6144 threads: one (b,ocg,ic,dz,og)
    if (idx < TOT) {
        int rr = idx;
        int og = rr & 3;          rr >>= 2;
        int dz = rr % 3;          rr /= 3;
        int ic = rr % CIN;        rr /= CIN;
        int ocg = rr % NOCG;
        int b   = rr / NOCG;
        int oc  = ocg * OCG + og;

        float g[3][3];
        #pragma unroll
        for (int ky = 0; ky < 3; ky++)
            #pragma unroll
            for (int kx = 0; kx < 3; kx++) {
                float s = 0.0f;
                #pragma unroll
                for (int e = 0; e < E_; e++)
                    s = fmaf(r[b][e],
                             ek[((e * COUT + oc) * CIN + ic) * 27 + dz * 9 + ky * 3 + kx], s);
                g[ky][kx] = s;
            }
        float T[4][3];
        #pragma unroll
        for (int kx = 0; kx < 3; kx++) {
            T[0][kx] = g[0][kx];
            T[1][kx] = 0.5f * (g[0][kx] + g[1][kx] + g[2][kx]);
            T[2][kx] = 0.5f * (g[0][kx] - g[1][kx] + g[2][kx]);
            T[3][kx] = g[2][kx];
        }
        float* dst = g_u + (size_t)(b * NOCG + ocg) * UBLK + (ic * 3 + dz) * 16 * OCG + og;
        #pragma unroll
        for (int i = 0; i < 4; i++) {
            float u0 = T[i][0];
            float u1 = 0.5f * (T[i][0] + T[i][1] + T[i][2]);
            float u2 = 0.5f * (T[i][0] - T[i][1] + T[i][2]);
            float u3 = T[i][2];
            dst[(i * 4 + 0) * 4] = u0;
            dst[(i * 4 + 1) * 4] = u1;
            dst[(i * 4 + 2) * 4] = u2;
            dst[(i * 4 + 3) * 4] = u3;
        }
    }
    if (idx < B_ * COUT) {
        int b = idx / COUT, o = idx - b * COUT;
        float s = 0.0f;
        #pragma unroll
        for (int e = 0; e < E_; e++) s = fmaf(r[b][e], eb[e * COUT + o], s);
        g_bias[idx] = s;
    }
    if (idx < COUT) { g_sum[idx] = 0.0f; g_sumsq[idx] = 0.0f; }
}

// ---------------------------------------------------------------------------
// Kernel 2: Winograd F(2x2,3x3) in (y,x), direct z. 4 oc per block.
// 160 thr = 2z x 4 ytiles x 20 xtiles; occupancy 2 (204-reg budget, no spill);
// x-transform fused into FMA loop (v computed 4-at-a-time, never stored).
// grid = (100, 8, 2)
// ---------------------------------------------------------------------------
__global__ void __launch_bounds__(NTHR, 2)
k_conv(const float* __restrict__ x) {
    extern __shared__ float dyn[];
    float* sh  = dyn;                    // [2][SLABVOL]
    float* ush = dyn + 2 * SLABVOL;      // [UBLK]
    float* red = ush + UBLK;             // [48]

    const int zt  = blockIdx.x / 5;
    const int yt  = blockIdx.x - 5 * zt;
    const int z0  = zt * ZT;
    const int y0  = yt * YT;
    const int ocg = blockIdx.y;
    const int b   = blockIdx.z;
    const int t   = threadIdx.x;

    for (int i = t; i < 2 * SLABVOL; i += NTHR) dyn[i] = 0.0f;
    const float* gu = g_u + (size_t)(b * NOCG + ocg) * UBLK;
    for (int i = t; i < UBLK; i += NTHR) ush[i] = gu[i];

    // ---- loader: 2 threads per row (t < 80), 5 x 16B cp.async each ----
    const float* xb = x + (size_t)(b * CIN) * SP;
    const int lrow = t >> 1;
    const int half = t & 1;
    const int lz = lrow / 10, ly2 = lrow - 10 * (lrow / 10);
    const int gz = z0 - 1 + lz, gy = y0 - 1 + ly2;
    const bool rowok = (t < 80) && ((unsigned)gz < D_) && ((unsigned)gy < D_);
    const long grow = (long)gz * 1600 + (long)gy * 40 + 20 * half;
    const unsigned sdst0 = (unsigned)__cvta_generic_to_shared(sh)
                         + (unsigned)(lrow * (SROW * 4) + 16 + 80 * half);

    auto prefetch = [&](int ic, int buf) {
        if (!rowok) return;
        const float* src = xb + (size_t)ic * SP + grow;
        unsigned d = sdst0 + (unsigned)buf * (SLABVOL * 4);
        #pragma unroll
        for (int c = 0; c < 5; c++)
            asm volatile("cp.async.cg.shared.global [%0], [%1], 16;"
                         :: "r"(d + c * 16), "l"(src + c * 4));
    };

    // ---- compute setup ----
    const int xt  = t % 20;              // x-tile: outputs 2xt, 2xt+1
    const int lyt = (t / 20) % 4;        // y-tile
    const int tz  = t / 80;              // local z

    float m[OCG][16];
    #pragma unroll
    for (int og = 0; og < OCG; og++)
        #pragma unroll
        for (int p = 0; p < 16; p++) m[og][p] = 0.0f;

    __syncthreads();
    prefetch(0, 0);
    asm volatile("cp.async.commit_group;");

    const int wbase = 2 + 2 * xt;

    for (int ic = 0; ic < CIN; ic++) {
        __syncthreads();
        if (ic + 1 < CIN) prefetch(ic + 1, (ic + 1) & 1);
        asm volatile("cp.async.commit_group;");
        asm volatile("cp.async.wait_group 1;");
        __syncthreads();

        const float* S = sh + (ic & 1) * SLABVOL;
        const float4* U4 = (const float4*)ush;
        #pragma unroll 1
        for (int dz = 0; dz < 3; dz++) {
            // load 4x4 patch (col-major temps: dJ[i] = row i, col J)
            float d0[4], d1[4], d2[4], d3[4];
            {
                const int rb0 = ((tz + dz) * 10 + 2 * lyt) * SROW + wbase;
                #pragma unroll
                for (int i = 0; i < 4; i++) {
                    const float* rp = S + rb0 + i * SROW;
                    float2 a = *(const float2*)(rp);
                    float2 bq = *(const float2*)(rp + 2);
                    float2 c = *(const float2*)(rp + 4);
                    d0[i] = a.y; d1[i] = bq.x; d2[i] = bq.y; d3[i] = c.x;
                }
            }
            // y-transform: cK[j] over rows
            float c0[4], c1[4], c2[4], c3[4];
            c0[0] = d0[0] - d0[2]; c1[0] = d0[1] + d0[2];
            c2[0] = d0[2] - d0[1]; c3[0] = d0[1] - d0[3];
            c0[1] = d1[0] - d1[2]; c1[1] = d1[1] + d1[2];
            c2[1] = d1[2] - d1[1]; c3[1] = d1[1] - d1[3];
            c0[2] = d2[0] - d2[2]; c1[2] = d2[1] + d2[2];
            c2[2] = d2[2] - d2[1]; c3[2] = d2[1] - d2[3];
            c0[3] = d3[0] - d3[2]; c1[3] = d3[1] + d3[2];
            c2[3] = d3[2] - d3[1]; c3[3] = d3[1] - d3[3];

            // fused x-transform + FMA, one k-row (4 positions) at a time
            const float4* Up = U4 + (ic * 3 + dz) * 16;
            #pragma unroll
            for (int k = 0; k < 4; k++) {
                float e0, e1, e2, e3;
                switch (k) {
                    case 0: e0 = c0[0]; e1 = c0[1]; e2 = c0[2]; e3 = c0[3]; break;
                    case 1: e0 = c1[0]; e1 = c1[1]; e2 = c1[2]; e3 = c1[3]; break;
                    case 2: e0 = c2[0]; e1 = c2[1]; e2 = c2[2]; e3 = c2[3]; break;
                    default: e0 = c3[0]; e1 = c3[1]; e2 = c3[2]; e3 = c3[3]; break;
                }
                float v0 = e0 - e2;
                float v1 = e1 + e2;
                float v2 = e2 - e1;
                float v3 = e1 - e3;
                float4 w;
                w = Up[k * 4 + 0];
                m[0][k*4+0] = fmaf(w.x, v0, m[0][k*4+0]);
                m[1][k*4+0] = fmaf(w.y, v0, m[1][k*4+0]);
                m[2][k*4+0] = fmaf(w.z, v0, m[2][k*4+0]);
                m[3][k*4+0] = fmaf(w.w, v0, m[3][k*4+0]);
                w = Up[k * 4 + 1];
                m[0][k*4+1] = fmaf(w.x, v1, m[0][k*4+1]);
                m[1][k*4+1] = fmaf(w.y, v1, m[1][k*4+1]);
                m[2][k*4+1] = fmaf(w.z, v1, m[2][k*4+1]);
                m[3][k*4+1] = fmaf(w.w, v1, m[3][k*4+1]);
                w = Up[k * 4 + 2];
                m[0][k*4+2] = fmaf(w.x, v2, m[0][k*4+2]);
                m[1][k*4+2] = fmaf(w.y, v2, m[1][k*4+2]);
                m[2][k*4+2] = fmaf(w.z, v2, m[2][k*4+2]);
                m[3][k*4+2] = fmaf(w.w, v2, m[3][k*4+2]);
                w = Up[k * 4 + 3];
                m[0][k*4+3] = fmaf(w.x, v3, m[0][k*4+3]);
                m[1][k*4+3] = fmaf(w.y, v3, m[1][k*4+3]);
                m[2][k*4+3] = fmaf(w.z, v3, m[2][k*4+3]);
                m[3][k*4+3] = fmaf(w.w, v3, m[3][k*4+3]);
            }
        }
    }

    // ---- epilogue: inverse transform A^T M A, bias, store, BN sums ----
    float s1[OCG], s2[OCG];
    #pragma unroll
    for (int og = 0; og < OCG; og++) { s1[og] = 0.0f; s2[og] = 0.0f; }

    {
        const int zo = z0 + tz, yo = y0 + 2 * lyt, xo = 2 * xt;
        #pragma unroll
        for (int og = 0; og < OCG; og++) {
            const int oc = ocg * OCG + og;
            const float bias = g_bias[b * COUT + oc];
            float r0[4], r1[4];
            #pragma unroll
            for (int j = 0; j < 4; j++) {
                r0[j] = m[og][0 * 4 + j] + m[og][1 * 4 + j] + m[og][2 * 4 + j];
                r1[j] = m[og][1 * 4 + j] - m[og][2 * 4 + j] - m[og][3 * 4 + j];
            }
            float y00 = r0[0] + r0[1] + r0[2] + bias;
            float y01 = r0[1] - r0[2] - r0[3] + bias;
            float y10 = r1[0] + r1[1] + r1[2] + bias;
            float y11 = r1[1] - r1[2] - r1[3] + bias;
            s1[og] += y00 + y01 + y10 + y11;
            s2[og] = fmaf(y00, y00, s2[og]);
            s2[og] = fmaf(y01, y01, s2[og]);
            s2[og] = fmaf(y10, y10, s2[og]);
            s2[og] = fmaf(y11, y11, s2[og]);
            float* yp = g_y + (size_t)(b * COUT + oc) * SP + zo * 1600 + yo * 40 + xo;
            *(float2*)yp        = make_float2(y00, y01);
            *(float2*)(yp + 40) = make_float2(y10, y11);
        }
    }
    #pragma unroll
    for (int og = 0; og < OCG; og++) {
        #pragma unroll
        for (int o = 16; o > 0; o >>= 1) {
            s1[og] += __shfl_down_sync(0xffffffff, s1[og], o);
            s2[og] += __shfl_down_sync(0xffffffff, s2[og], o);
        }
    }
    const int wid = t >> 5, lane = t & 31;    // 5 warps
    __syncthreads();
    if (lane == 0) {
        #pragma unroll
        for (int og = 0; og < OCG; og++) {
            red[og * 5 + wid]      = s1[og];
            red[24 + og * 5 + wid] = s2[og];
        }
    }
    __syncthreads();
    if (t < OCG) {
        float a = 0.0f, q = 0.0f;
        #pragma unroll
        for (int i = 0; i < 5; i++) { a += red[t * 5 + i]; q += red[24 + t * 5 + i]; }
        atomicAdd(&g_sum[ocg * OCG + t], a);
        atomicAdd(&g_sumsq[ocg * OCG + t], q);
    }
}

// ---------------------------------------------------------------------------
// Kernel 3: finalize BN -> per-channel scale/shift
// ---------------------------------------------------------------------------
__global__ void k_stats(const float* __restrict__ gamma,
                        const float* __restrict__ beta) {
    int c = threadIdx.x;
    if (c < COUT) {
        const float n = (float)(B_ * SP);
        float mean = g_sum[c] / n;
        float var  = g_sumsq[c] / n - mean * mean;
        float sc = gamma[c] * rsqrtf(var + 1e-5f);
        g_scale[c] = sc;
        g_shift[c] = beta[c] - mean * sc;
    }
}

// ---------------------------------------------------------------------------
// Kernel 4: affine + LeakyReLU + nearest upsample x2
// ---------------------------------------------------------------------------
__global__ void __launch_bounds__(256)
k_up(float* __restrict__ out) {
    int idx = blockIdx.x * blockDim.x + threadIdx.x;
    if (idx >= YTOT / 2) return;
    int i2 = idx * 2;
    int xw = i2 % 40;
    int rest = i2 / 40;
    int yw = rest % 40; rest /= 40;
    int zw = rest % 40; rest /= 40;
    int c  = rest % COUT;
    int b  = rest / COUT;

    float2 v = *(const float2*)&g_y[i2];
    float sc = g_scale[c], sf = g_shift[c];
    float a0 = fmaf(sc, v.x, sf); a0 = (a0 >= 0.0f) ? a0 : 0.1f * a0;
    float a1 = fmaf(sc, v.y, sf); a1 = (a1 >= 0.0f) ? a1 : 0.1f * a1;
    float4 p = make_float4(a0, a0, a1, a1);

    size_t base = ((size_t)(b * COUT + c) * 512000u)
                + (size_t)(2 * zw) * 6400u + (size_t)(2 * yw) * 80u + (size_t)(2 * xw);
    float4* o4 = (float4*)(out + base);
    o4[0]    = p;
    o4[20]   = p;
    o4[1600] = p;
    o4[1620] = p;
}

// ---------------------------------------------------------------------------
extern "C" void kernel_launch(void* const* d_in, const int* in_sizes, int n_in,
                              void* d_out, int out_size) {
    const float* x     = (const float*)d_in[0];
    const float* emb   = (const float*)d_in[1];
    const float* rw    = (const float*)d_in[2];
    const float* rb    = (const float*)d_in[3];
    const float* ek    = (const float*)d_in[4];
    const float* eb    = (const float*)d_in[5];
    const float* gamma = (const float*)d_in[6];
    const float* beta  = (const float*)d_in[7];
    float* out = (float*)d_out;

    k_route<<<(B_ * NOCG * CIN * 3 * OCG + 255) / 256, 256>>>(emb, rw, rb, ek, eb);

    size_t shbytes = (size_t)(2 * SLABVOL + UBLK + 48) * sizeof(float);  // ~40 KB
    cudaFuncSetAttribute(k_conv, cudaFuncAttributeMaxDynamicSharedMemorySize, (int)shbytes);
    dim3 gconv(100, NOCG, B_);
    k_conv<<<gconv, NTHR, shbytes>>>(x);

    k_stats<<<1, 32>>>(gamma, beta);

    k_up<<<(YTOT / 2 + 255) / 256, 256>>>(out);
}

// round 14
// speedup vs baseline: 1.1492x; 1.1492x over previous
#include <cuda_runtime.h>
#include <math.h>

#define B_    2
#define CIN   32
#define COUT  32
#define D_    40
#define E_    3
#define SP    (D_*D_*D_)          // 64000
#define YTOT  (B_*COUT*SP)        // 4,096,000
#define OCG   4                   // output channels per block
#define NOCG  (COUT/OCG)          // 8
#define ZT    2                   // z-outputs per block
#define YT    8                   // y-rows per block
#define SROW  48                  // padded smem row stride (floats)
#define NROWS ((ZT+2)*(YT+2))     // 40 rows (4 z-planes x 10 y-rows)
#define SLABVOL (NROWS*SROW)      // 1920 floats
#define WBLK  (CIN*27*OCG)        // 3456 weights per block
#define WICS  (27*OCG)            // 108 weights per ic
#define NTHR  160

// ---- scratch (device globals; no runtime allocation) ----
__device__ float g_w[B_*NOCG*WBLK];     // [b][ocg][ic][ky][dz][kx][oc4]
__device__ float g_bias[B_*COUT];
__device__ float g_y[YTOT];             // pre-upsample activations (16.4 MB)
__device__ float g_sum[COUT];
__device__ float g_sumsq[COUT];
__device__ float g_scale[COUT];
__device__ float g_shift[COUT];

// ---------------------------------------------------------------------------
// Kernel 1: routing + combined weights (blocked layout) + bias, zero stats
// ---------------------------------------------------------------------------
__global__ void k_route(const float* __restrict__ emb,
                        const float* __restrict__ rw,
                        const float* __restrict__ rb,
                        const float* __restrict__ ek,
                        const float* __restrict__ eb) {
    float r[B_][E_];
    #pragma unroll
    for (int b = 0; b < B_; b++)
        #pragma unroll
        for (int e = 0; e < E_; e++) {
            float t = fmaf(emb[b], rw[e], rb[e]);
            r[b][e] = 1.0f / (1.0f + expf(-t));
        }

    int idx = blockIdx.x * blockDim.x + threadIdx.x;
    const int TOT = B_ * NOCG * WBLK;   // 55296
    if (idx < TOT) {
        int rr = idx;
        int og = rr & 3;  rr >>= 2;
        int kx = rr % 3;  rr /= 3;
        int dz = rr % 3;  rr /= 3;
        int ky = rr % 3;  rr /= 3;
        int ic = rr % CIN; rr /= CIN;
        int ocg = rr % NOCG;
        int b   = rr / NOCG;
        int oc  = ocg * OCG + og;
        int tap = dz * 9 + ky * 3 + kx;
        float s = 0.0f;
        #pragma unroll
        for (int e = 0; e < E_; e++)
            s = fmaf(r[b][e], ek[((e * COUT + oc) * CIN + ic) * 27 + tap], s);
        g_w[idx] = s;
    }
    if (idx < B_ * COUT) {
        int b = idx / COUT, o = idx - b * COUT;
        float s = 0.0f;
        #pragma unroll
        for (int e = 0; e < E_; e++) s = fmaf(r[b][e], eb[e * COUT + o], s);
        g_bias[idx] = s;
    }
    if (idx < COUT) { g_sum[idx] = 0.0f; g_sumsq[idx] = 0.0f; }
}

// ---------------------------------------------------------------------------
// Kernel 2: direct 3x3x3 conv, 4 oc per block, tile 2z x 8y x 40x.
//   160 threads = 5 FULL warps, every lane computes 4x (zero lane waste).
//   4-buffer cp.async ring, 2 ic per pipeline stage (halved sync count).
// grid = (100 [zt*5+yt], 8 ocg, 2 b) = 1600 blocks
// ---------------------------------------------------------------------------
__global__ void __launch_bounds__(NTHR, 5)
k_conv(const float* __restrict__ x) {
    extern __shared__ float dyn[];
    float* sh  = dyn;                    // [4][SLABVOL]
    float* wsh = dyn + 4 * SLABVOL;      // [WBLK]
    float* red = wsh + WBLK;             // [48]

    const int zt  = blockIdx.x / 5;             // 0..19
    const int yt  = blockIdx.x - 5 * (blockIdx.x / 5);  // 0..4
    const int z0  = zt * ZT;
    const int y0  = yt * YT;
    const int ocg = blockIdx.y;                 // 0..7
    const int b   = blockIdx.z;                 // 0..1
    const int t   = threadIdx.x;

    // zero all 4 slab buffers once: halo rows/cols stay zero for all ic
    for (int i = t; i < 4 * SLABVOL; i += NTHR) dyn[i] = 0.0f;
    const float* gw = g_w + (size_t)(b * NOCG + ocg) * WBLK;
    for (int i = t; i < WBLK; i += NTHR) wsh[i] = gw[i];

    // ---- loader: 2 threads per row (t < 80), 5 x 16B cp.async each ----
    const float* xb = x + (size_t)(b * CIN) * SP;
    const int lrow = t >> 1;                   // 0..39 (t<80)
    const int half = t & 1;                    // 0/1: words 4..23 / 24..43
    const int lz = lrow / 10, ly2 = lrow - 10 * (lrow / 10);
    const int gz = z0 - 1 + lz, gy = y0 - 1 + ly2;
    const bool rowok = (t < 80) && ((unsigned)gz < D_) && ((unsigned)gy < D_);
    const long grow = (long)gz * 1600 + (long)gy * 40 + 20 * half;
    const unsigned sdst0 = (unsigned)__cvta_generic_to_shared(sh)
                         + (unsigned)(lrow * (SROW * 4) + 16 + 80 * half);

    auto prefetch = [&](int ic, int buf) {
        if (!rowok) return;
        const float* src = xb + (size_t)ic * SP + grow;
        unsigned d = sdst0 + (unsigned)buf * (SLABVOL * 4);
        #pragma unroll
        for (int c = 0; c < 5; c++)
            asm volatile("cp.async.cg.shared.global [%0], [%1], 16;"
                         :: "r"(d + c * 16), "l"(src + c * 4));
    };

    // ---- compute setup: all 160 threads compute ----
    const int k  = t % 10;                 // x-tile: outputs x = 4k..4k+3
    const int lyc = (t / 10) % 8;          // local y
    const int tz  = t / 80;                // 0/1 local z

    float acc[OCG][4];
    #pragma unroll
    for (int og = 0; og < OCG; og++)
        #pragma unroll
        for (int j = 0; j < 4; j++) acc[og][j] = 0.0f;

    __syncthreads();            // zero-fill visible before first prefetch
    prefetch(0, 0);
    asm volatile("cp.async.commit_group;");
    prefetch(1, 1);
    asm volatile("cp.async.commit_group;");

    const int rbase = 2 + 4 * k;           // even word: 4x LDS.64, uniform

    auto compute_ic = [&](int ic) {
        const float* S = sh + (ic & 3) * SLABVOL;
        const float* W = wsh + ic * WICS;   // [ky][dz][kx][oc4]
        #pragma unroll 1
        for (int ky = 0; ky < 3; ky++) {
            #pragma unroll
            for (int dz = 0; dz < 3; dz++) {
                const int row = (tz + dz) * 10 + lyc + ky;
                const float* rowp = S + row * SROW + rbase;
                float2 p0 = *(const float2*)(rowp);
                float2 p1 = *(const float2*)(rowp + 2);
                float2 p2 = *(const float2*)(rowp + 4);
                float2 p3 = *(const float2*)(rowp + 6);
                float f[6];
                f[0] = p0.y; f[1] = p1.x; f[2] = p1.y;
                f[3] = p2.x; f[4] = p2.y; f[5] = p3.x;
                #pragma unroll
                for (int kx = 0; kx < 3; kx++) {
                    float4 w4 = *(const float4*)(W + ((ky * 3 + dz) * 3 + kx) * 4);
                    #pragma unroll
                    for (int j = 0; j < 4; j++) {
                        acc[0][j] = fmaf(w4.x, f[j + kx], acc[0][j]);
                        acc[1][j] = fmaf(w4.y, f[j + kx], acc[1][j]);
                        acc[2][j] = fmaf(w4.z, f[j + kx], acc[2][j]);
                        acc[3][j] = fmaf(w4.w, f[j + kx], acc[3][j]);
                    }
                }
            }
        }
    };

    for (int ic = 0; ic < CIN; ic += 2) {
        __syncthreads();    // compute on bufs (ic+2)&3,(ic+3)&3 (stage ic-2) done
        if (ic + 2 < CIN) prefetch(ic + 2, (ic + 2) & 3);
        asm volatile("cp.async.commit_group;");
        if (ic + 3 < CIN) prefetch(ic + 3, (ic + 3) & 3);
        asm volatile("cp.async.commit_group;");
        asm volatile("cp.async.wait_group 2;");   // bufs ic&3, (ic+1)&3 ready
        __syncthreads();

        compute_ic(ic);
        compute_ic(ic + 1);
    }

    // ---- epilogue: bias, store y, BN partial sums (per og) ----
    float s1[OCG], s2[OCG];
    #pragma unroll
    for (int og = 0; og < OCG; og++) { s1[og] = 0.0f; s2[og] = 0.0f; }

    {
        const int zo = z0 + tz, yo = y0 + lyc, xo = 4 * k;
        #pragma unroll
        for (int og = 0; og < OCG; og++) {
            const int oc = ocg * OCG + og;
            const float bias = g_bias[b * COUT + oc];
            float* yp = g_y + (size_t)(b * COUT + oc) * SP
                      + zo * 1600 + yo * 40 + xo;
            float4 q; float v;
            v = acc[og][0] + bias; s1[og] += v; s2[og] = fmaf(v, v, s2[og]); q.x = v;
            v = acc[og][1] + bias; s1[og] += v; s2[og] = fmaf(v, v, s2[og]); q.y = v;
            v = acc[og][2] + bias; s1[og] += v; s2[og] = fmaf(v, v, s2[og]); q.z = v;
            v = acc[og][3] + bias; s1[og] += v; s2[og] = fmaf(v, v, s2[og]); q.w = v;
            *(float4*)yp = q;   // xo multiple of 4 -> 16B aligned
        }
    }
    #pragma unroll
    for (int og = 0; og < OCG; og++) {
        #pragma unroll
        for (int o = 16; o > 0; o >>= 1) {
            s1[og] += __shfl_down_sync(0xffffffff, s1[og], o);
            s2[og] += __shfl_down_sync(0xffffffff, s2[og], o);
        }
    }
    const int wid = t >> 5, lane = t & 31;    // 5 warps
    __syncthreads();
    if (lane == 0) {
        #pragma unroll
        for (int og = 0; og < OCG; og++) {
            red[og * 5 + wid]      = s1[og];
            red[24 + og * 5 + wid] = s2[og];
        }
    }
    __syncthreads();
    if (t < OCG) {
        float a = 0.0f, q = 0.0f;
        #pragma unroll
        for (int i = 0; i < 5; i++) { a += red[t * 5 + i]; q += red[24 + t * 5 + i]; }
        atomicAdd(&g_sum[ocg * OCG + t], a);
        atomicAdd(&g_sumsq[ocg * OCG + t], q);
    }
}

// ---------------------------------------------------------------------------
// Kernel 3: finalize BN -> per-channel scale/shift
// ---------------------------------------------------------------------------
__global__ void k_stats(const float* __restrict__ gamma,
                        const float* __restrict__ beta) {
    int c = threadIdx.x;
    if (c < COUT) {
        const float n = (float)(B_ * SP);
        float mean = g_sum[c] / n;
        float var  = g_sumsq[c] / n - mean * mean;
        float sc = gamma[c] * rsqrtf(var + 1e-5f);
        g_scale[c] = sc;
        g_shift[c] = beta[c] - mean * sc;
    }
}

// ---------------------------------------------------------------------------
// Kernel 4: affine + LeakyReLU + nearest upsample x2; float2 in, 4x float4 out
// ---------------------------------------------------------------------------
__global__ void __launch_bounds__(256)
k_up(float* __restrict__ out) {
    int idx = blockIdx.x * blockDim.x + threadIdx.x;  // over YTOT/2
    if (idx >= YTOT / 2) return;
    int i2 = idx * 2;
    int xw = i2 % 40;                 // even
    int rest = i2 / 40;
    int yw = rest % 40; rest /= 40;
    int zw = rest % 40; rest /= 40;
    int c  = rest % COUT;
    int b  = rest / COUT;

    float2 v = *(const float2*)&g_y[i2];
    float sc = g_scale[c], sf = g_shift[c];
    float a0 = fmaf(sc, v.x, sf); a0 = (a0 >= 0.0f) ? a0 : 0.1f * a0;
    float a1 = fmaf(sc, v.y, sf); a1 = (a1 >= 0.0f) ? a1 : 0.1f * a1;
    float4 p = make_float4(a0, a0, a1, a1);

    size_t base = ((size_t)(b * COUT + c) * 512000u)
                + (size_t)(2 * zw) * 6400u + (size_t)(2 * yw) * 80u + (size_t)(2 * xw);
    float4* o4 = (float4*)(out + base);
    o4[0]    = p;    // (2z,   2y  )
    o4[20]   = p;    // (2z,   2y+1)
    o4[1600] = p;    // (2z+1, 2y  )
    o4[1620] = p;    // (2z+1, 2y+1)
}

// ---------------------------------------------------------------------------
extern "C" void kernel_launch(void* const* d_in, const int* in_sizes, int n_in,
                              void* d_out, int out_size) {
    const float* x     = (const float*)d_in[0];
    const float* emb   = (const float*)d_in[1];
    const float* rw    = (const float*)d_in[2];
    const float* rb    = (const float*)d_in[3];
    const float* ek    = (const float*)d_in[4];
    const float* eb    = (const float*)d_in[5];
    const float* gamma = (const float*)d_in[6];
    const float* beta  = (const float*)d_in[7];
    float* out = (float*)d_out;

    k_route<<<(B_ * NOCG * WBLK + 255) / 256, 256>>>(emb, rw, rb, ek, eb);

    size_t shbytes = (size_t)(4 * SLABVOL + WBLK + 48) * sizeof(float);  // ~44.7 KB
    cudaFuncSetAttribute(k_conv, cudaFuncAttributeMaxDynamicSharedMemorySize, (int)shbytes);
    dim3 gconv(100, NOCG, B_);
    k_conv<<<gconv, NTHR, shbytes>>>(x);

    k_stats<<<1, 32>>>(gamma, beta);

    k_up<<<(YTOT / 2 + 255) / 256, 256>>>(out);
}

// round 15
// speedup vs baseline: 1.1767x; 1.0239x over previous
#include <cuda_runtime.h>
#include <math.h>

#define B_    2
#define CIN   32
#define COUT  32
#define D_    40
#define E_    3
#define SP    (D_*D_*D_)          // 64000
#define YTOT  (B_*COUT*SP)        // 4,096,000
#define OCG   4                   // output channels per block
#define NOCG  (COUT/OCG)          // 8
#define ZT    2                   // z-outputs per block
#define YT    8                   // y-rows per block
#define SROW  48                  // padded smem row stride (floats)
#define NROWS ((ZT+2)*(YT+2))     // 40 rows (4 z-planes x 10 y-rows)
#define SLABVOL (NROWS*SROW)      // 1920 floats
#define WBLK  (CIN*27*OCG)        // 3456 weights per block
#define WICS  (27*OCG)            // 108 weights per ic
#define NTHR  160

// ---- scratch (device globals; no runtime allocation) ----
__device__ float g_w[B_*NOCG*WBLK];     // [b][ocg][ic][ky][dz][kx][oc4]
__device__ float g_bias[B_*COUT];
__device__ float g_y[YTOT];             // pre-upsample activations (16.4 MB)
__device__ float g_sum[COUT];
__device__ float g_sumsq[COUT];

// ---------------------------------------------------------------------------
// Kernel 1: routing + combined weights (blocked layout) + bias, zero stats
// ---------------------------------------------------------------------------
__global__ void k_route(const float* __restrict__ emb,
                        const float* __restrict__ rw,
                        const float* __restrict__ rb,
                        const float* __restrict__ ek,
                        const float* __restrict__ eb) {
    float r[B_][E_];
    #pragma unroll
    for (int b = 0; b < B_; b++)
        #pragma unroll
        for (int e = 0; e < E_; e++) {
            float t = fmaf(emb[b], rw[e], rb[e]);
            r[b][e] = 1.0f / (1.0f + expf(-t));
        }

    int idx = blockIdx.x * blockDim.x + threadIdx.x;
    const int TOT = B_ * NOCG * WBLK;   // 55296
    if (idx < TOT) {
        int rr = idx;
        int og = rr & 3;  rr >>= 2;
        int kx = rr % 3;  rr /= 3;
        int dz = rr % 3;  rr /= 3;
        int ky = rr % 3;  rr /= 3;
        int ic = rr % CIN; rr /= CIN;
        int ocg = rr % NOCG;
        int b   = rr / NOCG;
        int oc  = ocg * OCG + og;
        int tap = dz * 9 + ky * 3 + kx;
        float s = 0.0f;
        #pragma unroll
        for (int e = 0; e < E_; e++)
            s = fmaf(r[b][e], ek[((e * COUT + oc) * CIN + ic) * 27 + tap], s);
        g_w[idx] = s;
    }
    if (idx < B_ * COUT) {
        int b = idx / COUT, o = idx - b * COUT;
        float s = 0.0f;
        #pragma unroll
        for (int e = 0; e < E_; e++) s = fmaf(r[b][e], eb[e * COUT + o], s);
        g_bias[idx] = s;
    }
    if (idx < COUT) { g_sum[idx] = 0.0f; g_sumsq[idx] = 0.0f; }
}

// ---------------------------------------------------------------------------
// Kernel 2: direct 3x3x3 conv, 4 oc per block, tile 2z x 8y x 40x.
//   160 threads = 5 FULL warps, every lane computes 4x (zero lane waste).
//   Weights + first slab prefetched via cp.async in one prologue group.
// grid = (100 [zt*5+yt], 8 ocg, 2 b) = 1600 blocks
// ---------------------------------------------------------------------------
__global__ void __launch_bounds__(NTHR, 5)
k_conv(const float* __restrict__ x) {
    extern __shared__ float dyn[];
    float* sh  = dyn;                    // [2][SLABVOL]
    float* wsh = dyn + 2 * SLABVOL;      // [WBLK]
    float* red = wsh + WBLK;             // [48]

    const int zt  = blockIdx.x / 5;             // 0..19
    const int yt  = blockIdx.x - 5 * (blockIdx.x / 5);  // 0..4
    const int z0  = zt * ZT;
    const int y0  = yt * YT;
    const int ocg = blockIdx.y;                 // 0..7
    const int b   = blockIdx.z;                 // 0..1
    const int t   = threadIdx.x;

    // zero slabs once: halo rows/cols stay zero for all ic
    for (int i = t; i < 2 * SLABVOL; i += NTHR) dyn[i] = 0.0f;

    // weights via cp.async (overlapped with first slab fill): 864 x 16B chunks
    {
        const float* gw = g_w + (size_t)(b * NOCG + ocg) * WBLK;
        unsigned wdst = (unsigned)__cvta_generic_to_shared(wsh);
        for (int i = t; i < WBLK / 4; i += NTHR)
            asm volatile("cp.async.cg.shared.global [%0], [%1], 16;"
                         :: "r"(wdst + i * 16), "l"(gw + i * 4));
    }

    // ---- loader: 2 threads per row (t < 80), 5 x 16B cp.async each ----
    const float* xb = x + (size_t)(b * CIN) * SP;
    const int lrow = t >> 1;                   // 0..39 (t<80)
    const int half = t & 1;                    // 0/1: words 4..23 / 24..43
    const int lz = lrow / 10, ly2 = lrow - 10 * (lrow / 10);
    const int gz = z0 - 1 + lz, gy = y0 - 1 + ly2;
    const bool rowok = (t < 80) && ((unsigned)gz < D_) && ((unsigned)gy < D_);
    const long grow = (long)gz * 1600 + (long)gy * 40 + 20 * half;
    const unsigned sdst0 = (unsigned)__cvta_generic_to_shared(sh)
                         + (unsigned)(lrow * (SROW * 4) + 16 + 80 * half);

    auto prefetch = [&](int ic, int buf) {
        if (!rowok) return;
        const float* src = xb + (size_t)ic * SP + grow;
        unsigned d = sdst0 + (unsigned)buf * (SLABVOL * 4);
        #pragma unroll
        for (int c = 0; c < 5; c++)
            asm volatile("cp.async.cg.shared.global [%0], [%1], 16;"
                         :: "r"(d + c * 16), "l"(src + c * 4));
    };

    // ---- compute setup: all 160 threads compute ----
    const int k  = t % 10;                 // x-tile: outputs x = 4k..4k+3
    const int lyc = (t / 10) % 8;          // local y
    const int tz  = t / 80;                // 0/1 local z

    float acc[OCG][4];
    #pragma unroll
    for (int og = 0; og < OCG; og++)
        #pragma unroll
        for (int j = 0; j < 4; j++) acc[og][j] = 0.0f;

    __syncthreads();            // zero-fill visible before first prefetch
    prefetch(0, 0);             // joins the weight group
    asm volatile("cp.async.commit_group;");

    const int rbase = 2 + 4 * k;           // even word: 4x LDS.64, uniform

    for (int ic = 0; ic < CIN; ic++) {
        __syncthreads();
        if (ic + 1 < CIN) prefetch(ic + 1, (ic + 1) & 1);
        asm volatile("cp.async.commit_group;");
        asm volatile("cp.async.wait_group 1;");   // buffer ic&1 (and weights) ready
        __syncthreads();

        const float* S = sh + (ic & 1) * SLABVOL;
        const float* W = wsh + ic * WICS;   // [ky][dz][kx][oc4]
        #pragma unroll 1
        for (int ky = 0; ky < 3; ky++) {
            #pragma unroll
            for (int dz = 0; dz < 3; dz++) {
                const int row = (tz + dz) * 10 + lyc + ky;
                const float* rowp = S + row * SROW + rbase;
                float2 p0 = *(const float2*)(rowp);
                float2 p1 = *(const float2*)(rowp + 2);
                float2 p2 = *(const float2*)(rowp + 4);
                float2 p3 = *(const float2*)(rowp + 6);
                float f[6];
                f[0] = p0.y; f[1] = p1.x; f[2] = p1.y;
                f[3] = p2.x; f[4] = p2.y; f[5] = p3.x;
                #pragma unroll
                for (int kx = 0; kx < 3; kx++) {
                    float4 w4 = *(const float4*)(W + ((ky * 3 + dz) * 3 + kx) * 4);
                    #pragma unroll
                    for (int j = 0; j < 4; j++) {
                        acc[0][j] = fmaf(w4.x, f[j + kx], acc[0][j]);
                        acc[1][j] = fmaf(w4.y, f[j + kx], acc[1][j]);
                        acc[2][j] = fmaf(w4.z, f[j + kx], acc[2][j]);
                        acc[3][j] = fmaf(w4.w, f[j + kx], acc[3][j]);
                    }
                }
            }
        }
    }

    // ---- epilogue: bias, store y, BN partial sums (per og) ----
    float s1[OCG], s2[OCG];
    #pragma unroll
    for (int og = 0; og < OCG; og++) { s1[og] = 0.0f; s2[og] = 0.0f; }

    {
        const int zo = z0 + tz, yo = y0 + lyc, xo = 4 * k;
        #pragma unroll
        for (int og = 0; og < OCG; og++) {
            const int oc = ocg * OCG + og;
            const float bias = g_bias[b * COUT + oc];
            float* yp = g_y + (size_t)(b * COUT + oc) * SP
                      + zo * 1600 + yo * 40 + xo;
            float4 q; float v;
            v = acc[og][0] + bias; s1[og] += v; s2[og] = fmaf(v, v, s2[og]); q.x = v;
            v = acc[og][1] + bias; s1[og] += v; s2[og] = fmaf(v, v, s2[og]); q.y = v;
            v = acc[og][2] + bias; s1[og] += v; s2[og] = fmaf(v, v, s2[og]); q.z = v;
            v = acc[og][3] + bias; s1[og] += v; s2[og] = fmaf(v, v, s2[og]); q.w = v;
            *(float4*)yp = q;   // xo multiple of 4 -> 16B aligned
        }
    }
    #pragma unroll
    for (int og = 0; og < OCG; og++) {
        #pragma unroll
        for (int o = 16; o > 0; o >>= 1) {
            s1[og] += __shfl_down_sync(0xffffffff, s1[og], o);
            s2[og] += __shfl_down_sync(0xffffffff, s2[og], o);
        }
    }
    const int wid = t >> 5, lane = t & 31;    // 5 warps
    __syncthreads();
    if (lane == 0) {
        #pragma unroll
        for (int og = 0; og < OCG; og++) {
            red[og * 5 + wid]      = s1[og];
            red[24 + og * 5 + wid] = s2[og];
        }
    }
    __syncthreads();
    if (t < OCG) {
        float a = 0.0f, q = 0.0f;
        #pragma unroll
        for (int i = 0; i < 5; i++) { a += red[t * 5 + i]; q += red[24 + t * 5 + i]; }
        atomicAdd(&g_sum[ocg * OCG + t], a);
        atomicAdd(&g_sumsq[ocg * OCG + t], q);
    }
}

// ---------------------------------------------------------------------------
// Kernel 3 (fused former k_stats): affine + LeakyReLU + upsample x2.
// Per-thread BN finalize from g_sum/g_sumsq (L2-broadcast, ~free here).
// ---------------------------------------------------------------------------
__global__ void __launch_bounds__(256)
k_up(const float* __restrict__ gamma, const float* __restrict__ beta,
     float* __restrict__ out) {
    int idx = blockIdx.x * blockDim.x + threadIdx.x;  // over YTOT/2
    if (idx >= YTOT / 2) return;
    int i2 = idx * 2;
    int xw = i2 % 40;                 // even
    int rest = i2 / 40;
    int yw = rest % 40; rest /= 40;
    int zw = rest % 40; rest /= 40;
    int c  = rest % COUT;
    int b  = rest / COUT;

    const float invn = 1.0f / (float)(B_ * SP);
    float mean = g_sum[c] * invn;
    float var  = g_sumsq[c] * invn - mean * mean;
    float sc = gamma[c] * rsqrtf(var + 1e-5f);
    float sf = beta[c] - mean * sc;

    float2 v = *(const float2*)&g_y[i2];
    float a0 = fmaf(sc, v.x, sf); a0 = (a0 >= 0.0f) ? a0 : 0.1f * a0;
    float a1 = fmaf(sc, v.y, sf); a1 = (a1 >= 0.0f) ? a1 : 0.1f * a1;
    float4 p = make_float4(a0, a0, a1, a1);

    size_t base = ((size_t)(b * COUT + c) * 512000u)
                + (size_t)(2 * zw) * 6400u + (size_t)(2 * yw) * 80u + (size_t)(2 * xw);
    float4* o4 = (float4*)(out + base);
    o4[0]    = p;    // (2z,   2y  )
    o4[20]   = p;    // (2z,   2y+1)
    o4[1600] = p;    // (2z+1, 2y  )
    o4[1620] = p;    // (2z+1, 2y+1)
}

// ---------------------------------------------------------------------------
extern "C" void kernel_launch(void* const* d_in, const int* in_sizes, int n_in,
                              void* d_out, int out_size) {
    const float* x     = (const float*)d_in[0];
    const float* emb   = (const float*)d_in[1];
    const float* rw    = (const float*)d_in[2];
    const float* rb    = (const float*)d_in[3];
    const float* ek    = (const float*)d_in[4];
    const float* eb    = (const float*)d_in[5];
    const float* gamma = (const float*)d_in[6];
    const float* beta  = (const float*)d_in[7];
    float* out = (float*)d_out;

    k_route<<<(B_ * NOCG * WBLK + 255) / 256, 256>>>(emb, rw, rb, ek, eb);

    size_t shbytes = (size_t)(2 * SLABVOL + WBLK + 48) * sizeof(float);  // ~29.5 KB
    cudaFuncSetAttribute(k_conv, cudaFuncAttributeMaxDynamicSharedMemorySize, (int)shbytes);
    dim3 gconv(100, NOCG, B_);
    k_conv<<<gconv, NTHR, shbytes>>>(x);

    k_up<<<(YTOT / 2 + 255) / 256, 256>>>(gamma, beta, out);
}

// round 16
// speedup vs baseline: 2.3295x; 1.9797x over previous
#include <cuda_runtime.h>
#include <math.h>

#define B_    2
#define CIN   32
#define COUT  32
#define D_    40
#define E_    3
#define SP    64000
#define YTOT  4096000
#define YT    8
#define SROW  48
#define SLABROWS 30               // 3 z-planes x 10 y-rows
#define SLABVOL (SLABROWS*SROW)   // 1440 floats
#define WV    1024                // 32 k x 32 oc per ic (tf32 bits)
#define NTHR  160

// ---- scratch (device globals; no runtime allocation) ----
__device__ unsigned g_wt[B_*CIN*WV];   // [b][ic][k32][oc32] tf32 bits (k>=27 zero)
__device__ float g_bias[B_*COUT];
__device__ float g_y[YTOT];
__device__ float g_sum[COUT];
__device__ float g_sumsq[COUT];

__device__ __forceinline__ void mma_tf32(float* c, const unsigned* a,
                                         unsigned b0, unsigned b1) {
    asm volatile(
        "mma.sync.aligned.m16n8k8.row.col.f32.tf32.tf32.f32 "
        "{%0,%1,%2,%3}, {%4,%5,%6,%7}, {%8,%9}, {%0,%1,%2,%3};\n"
        : "+f"(c[0]), "+f"(c[1]), "+f"(c[2]), "+f"(c[3])
        : "r"(a[0]), "r"(a[1]), "r"(a[2]), "r"(a[3]), "r"(b0), "r"(b1));
}
__device__ __forceinline__ unsigned to_tf32(float f) {
    unsigned u;
    asm("cvt.rna.tf32.f32 %0, %1;" : "=r"(u) : "f"(f));
    return u;
}

// ---------------------------------------------------------------------------
// Kernel 1: routing + combined weights as tf32 bits [b][ic][k32][oc32] + bias
// ---------------------------------------------------------------------------
__global__ void k_route(const float* __restrict__ emb,
                        const float* __restrict__ rw,
                        const float* __restrict__ rb,
                        const float* __restrict__ ek,
                        const float* __restrict__ eb) {
    float r[B_][E_];
    #pragma unroll
    for (int b = 0; b < B_; b++)
        #pragma unroll
        for (int e = 0; e < E_; e++) {
            float t = fmaf(emb[b], rw[e], rb[e]);
            r[b][e] = 1.0f / (1.0f + expf(-t));
        }

    int idx = blockIdx.x * blockDim.x + threadIdx.x;
    if (idx < B_ * CIN * WV) {           // 65536
        int oc = idx & 31;
        int k  = (idx >> 5) & 31;
        int ic = (idx >> 10) & 31;
        int b  = idx >> 15;
        unsigned u = 0u;
        if (k < 27) {
            float s = 0.0f;
            #pragma unroll
            for (int e = 0; e < E_; e++)
                s = fmaf(r[b][e], ek[((e * COUT + oc) * CIN + ic) * 27 + k], s);
            u = to_tf32(s);
        }
        g_wt[idx] = u;
    }
    if (idx < B_ * COUT) {
        int b = idx / COUT, o = idx - b * COUT;
        float s = 0.0f;
        #pragma unroll
        for (int e = 0; e < E_; e++) s = fmaf(r[b][e], eb[e * COUT + o], s);
        g_bias[idx] = s;
    }
    if (idx < COUT) { g_sum[idx] = 0.0f; g_sumsq[idx] = 0.0f; }
}

// ---------------------------------------------------------------------------
// Kernel 2: TF32 warp-MMA implicit conv. Tile 1z x 8y x 40x, all 32 oc.
// 5 warps; warp w owns colgroups w*8..w*8+7 (8 spatial each), C[8][2][4].
// K = ic(32) x k32 (27 taps + 5 zero-pad). grid = (200 [z*5+yt], 2 b)
// ---------------------------------------------------------------------------
__global__ void __launch_bounds__(NTHR, 3)
k_conv(const float* __restrict__ x) {
    extern __shared__ float dyn[];
    float* sh      = dyn;                              // [2][SLABVOL]
    unsigned* wsh  = (unsigned*)(dyn + 2 * SLABVOL);   // [2][WV]
    float* red     = dyn + 2 * SLABVOL + 2 * WV;       // [320]

    const int z0 = blockIdx.x / 5;
    const int y0 = (blockIdx.x % 5) * YT;
    const int b  = blockIdx.y;
    const int t  = threadIdx.x;
    const int lane = t & 31, w = t >> 5;
    const int g = lane >> 2, tg = lane & 3;

    for (int i = t; i < 2 * SLABVOL + 2 * WV + 320; i += NTHR) dyn[i] = 0.0f;

    // ---- loaders ----
    const float* xb = x + (size_t)(b * CIN) * SP;
    const int lrow = t >> 1, hlf = t & 1;
    const int lz = lrow / 10, ly2 = lrow % 10;
    const int gz = z0 - 1 + lz, gy = y0 - 1 + ly2;
    const bool rowok = (t < 60) && ((unsigned)gz < D_) && ((unsigned)gy < D_);
    const long grow = (long)gz * 1600 + (long)gy * 40 + 20 * hlf;
    const unsigned sdst0 = (unsigned)__cvta_generic_to_shared(sh)
                         + (unsigned)(lrow * (SROW * 4) + 16 + 80 * hlf);
    const unsigned* gwb = g_wt + (size_t)b * CIN * WV;
    const unsigned wdst0 = (unsigned)__cvta_generic_to_shared(wsh);

    auto prefetch = [&](int ic, int buf) {
        if (rowok) {
            const float* src = xb + (size_t)ic * SP + grow;
            unsigned d = sdst0 + (unsigned)buf * (SLABVOL * 4);
            #pragma unroll
            for (int c = 0; c < 5; c++)
                asm volatile("cp.async.cg.shared.global [%0], [%1], 16;"
                             :: "r"(d + c * 16), "l"(src + c * 4));
        }
        const unsigned* sw = gwb + ic * WV;
        unsigned dw = wdst0 + (unsigned)buf * (WV * 4);
        for (int i = t; i < WV / 4; i += NTHR)
            asm volatile("cp.async.cg.shared.global [%0], [%1], 16;"
                         :: "r"(dw + i * 16), "l"(sw + i * 4));
    };

    // ---- per-lane gather offsets ----
    int off0[4], off1[4];
    #pragma unroll
    for (int kc = 0; kc < 4; kc++) {
        int kr = tg + 8 * kc;
        off0[kc] = (kr < 27) ? ((kr / 9) * 10 + (kr % 9) / 3) * SROW + (kr % 3) : 0;
        kr += 4;
        off1[kc] = (kr < 27) ? ((kr / 9) * 10 + (kr % 9) / 3) * SROW + (kr % 3) : 0;
    }
    int cgb[8];
    #pragma unroll
    for (int j = 0; j < 8; j++) {
        int cgg = w * 8 + j;
        cgb[j] = (cgg / 5) * SROW + 3 + (cgg % 5) * 8 + g;
    }

    float C[8][2][4];
    #pragma unroll
    for (int j = 0; j < 8; j++)
        #pragma unroll
        for (int h = 0; h < 2; h++)
            #pragma unroll
            for (int q = 0; q < 4; q++) C[j][h][q] = 0.0f;

    __syncthreads();
    prefetch(0, 0);
    asm volatile("cp.async.commit_group;");

    for (int ic = 0; ic < CIN; ic++) {
        __syncthreads();
        if (ic + 1 < CIN) prefetch(ic + 1, (ic + 1) & 1);
        asm volatile("cp.async.commit_group;");
        asm volatile("cp.async.wait_group 1;");
        __syncthreads();

        const float* S = sh + (ic & 1) * SLABVOL;
        const unsigned* Wm = wsh + (ic & 1) * WV;

        unsigned A[2][4][4];
        #pragma unroll
        for (int h = 0; h < 2; h++)
            #pragma unroll
            for (int kc = 0; kc < 4; kc++) {
                int c0 = (tg + 8 * kc) * 32, c1 = (tg + 4 + 8 * kc) * 32;
                int r0 = g + 16 * h, r1 = r0 + 8;
                A[h][kc][0] = Wm[c0 + r0];
                A[h][kc][1] = Wm[c0 + r1];
                A[h][kc][2] = Wm[c1 + r0];
                A[h][kc][3] = Wm[c1 + r1];
            }

        #pragma unroll
        for (int j = 0; j < 8; j++) {
            const float* Sj = S + cgb[j];
            #pragma unroll
            for (int kc = 0; kc < 4; kc++) {
                unsigned b0 = to_tf32(Sj[off0[kc]]);
                unsigned b1 = to_tf32(Sj[off1[kc]]);
                mma_tf32(C[j][0], A[0][kc], b0, b1);
                mma_tf32(C[j][1], A[1][kc], b0, b1);
            }
        }
    }

    // ---- epilogue: bias, store y, BN partial sums ----
    float s1[4] = {0.f, 0.f, 0.f, 0.f}, s2[4] = {0.f, 0.f, 0.f, 0.f};
    float bia[4];
    #pragma unroll
    for (int q = 0; q < 4; q++) bia[q] = g_bias[b * COUT + g + 8 * q];

    #pragma unroll
    for (int j = 0; j < 8; j++) {
        int cgg = w * 8 + j;
        size_t sp = (size_t)z0 * 1600 + (size_t)(y0 + cgg / 5) * 40
                  + (cgg % 5) * 8 + 2 * tg;
        #pragma unroll
        for (int h = 0; h < 2; h++) {
            int oclo = g + 16 * h, ochi = oclo + 8;
            float blo = bia[2 * h], bhi = bia[2 * h + 1];
            float v0 = C[j][h][0] + blo, v1 = C[j][h][1] + blo;
            float v2 = C[j][h][2] + bhi, v3 = C[j][h][3] + bhi;
            s1[2*h]   += v0 + v1; s2[2*h]   = fmaf(v0, v0, fmaf(v1, v1, s2[2*h]));
            s1[2*h+1] += v2 + v3; s2[2*h+1] = fmaf(v2, v2, fmaf(v3, v3, s2[2*h+1]));
            *(float2*)(g_y + (size_t)(b * COUT + oclo) * SP + sp) = make_float2(v0, v1);
            *(float2*)(g_y + (size_t)(b * COUT + ochi) * SP + sp) = make_float2(v2, v3);
        }
    }
    #pragma unroll
    for (int q = 0; q < 4; q++) {
        s1[q] += __shfl_down_sync(0xffffffffu, s1[q], 2, 4);
        s1[q] += __shfl_down_sync(0xffffffffu, s1[q], 1, 4);
        s2[q] += __shfl_down_sync(0xffffffffu, s2[q], 2, 4);
        s2[q] += __shfl_down_sync(0xffffffffu, s2[q], 1, 4);
    }
    __syncthreads();
    if (tg == 0) {
        #pragma unroll
        for (int q = 0; q < 4; q++) {
            red[(g + 8 * q) * 5 + w]       = s1[q];
            red[160 + (g + 8 * q) * 5 + w] = s2[q];
        }
    }
    __syncthreads();
    if (t < COUT) {
        float a = 0.0f, qq = 0.0f;
        #pragma unroll
        for (int i = 0; i < 5; i++) { a += red[t * 5 + i]; qq += red[160 + t * 5 + i]; }
        atomicAdd(&g_sum[t], a);
        atomicAdd(&g_sumsq[t], qq);
    }
}

// ---------------------------------------------------------------------------
// Kernel 3: BN finalize + affine + LeakyReLU + nearest upsample x2
// ---------------------------------------------------------------------------
__global__ void __launch_bounds__(256)
k_up(const float* __restrict__ gamma, const float* __restrict__ beta,
     float* __restrict__ out) {
    int idx = blockIdx.x * blockDim.x + threadIdx.x;  // over YTOT/2
    if (idx >= YTOT / 2) return;
    int i2 = idx * 2;
    int xw = i2 % 40;
    int rest = i2 / 40;
    int yw = rest % 40; rest /= 40;
    int zw = rest % 40; rest /= 40;
    int c  = rest % COUT;
    int b  = rest / COUT;

    const float invn = 1.0f / (float)(B_ * SP);
    float mean = g_sum[c] * invn;
    float var  = g_sumsq[c] * invn - mean * mean;
    float sc = gamma[c] * rsqrtf(var + 1e-5f);
    float sf = beta[c] - mean * sc;

    float2 v = *(const float2*)&g_y[i2];
    float a0 = fmaf(sc, v.x, sf); a0 = (a0 >= 0.0f) ? a0 : 0.1f * a0;
    float a1 = fmaf(sc, v.y, sf); a1 = (a1 >= 0.0f) ? a1 : 0.1f * a1;
    float4 p = make_float4(a0, a0, a1, a1);

    size_t base = ((size_t)(b * COUT + c) * 512000u)
                + (size_t)(2 * zw) * 6400u + (size_t)(2 * yw) * 80u + (size_t)(2 * xw);
    float4* o4 = (float4*)(out + base);
    o4[0]    = p;
    o4[20]   = p;
    o4[1600] = p;
    o4[1620] = p;
}

// ---------------------------------------------------------------------------
extern "C" void kernel_launch(void* const* d_in, const int* in_sizes, int n_in,
                              void* d_out, int out_size) {
    const float* x     = (const float*)d_in[0];
    const float* emb   = (const float*)d_in[1];
    const float* rw    = (const float*)d_in[2];
    const float* rb    = (const float*)d_in[3];
    const float* ek    = (const float*)d_in[4];
    const float* eb    = (const float*)d_in[5];
    const float* gamma = (const float*)d_in[6];
    const float* beta  = (const float*)d_in[7];
    float* out = (float*)d_out;

    k_route<<<(B_ * CIN * WV + 255) / 256, 256>>>(emb, rw, rb, ek, eb);

    size_t shbytes = (size_t)(2 * SLABVOL + 2 * WV + 320) * sizeof(float);  // ~21 KB
    cudaFuncSetAttribute(k_conv, cudaFuncAttributeMaxDynamicSharedMemorySize, (int)shbytes);
    dim3 gconv(200, B_);
    k_conv<<<gconv, NTHR, shbytes>>>(x);

    k_up<<<(YTOT / 2 + 255) / 256, 256>>>(gamma, beta, out);
}

// round 17
// speedup vs baseline: 2.6984x; 1.1583x over previous
#include <cuda_runtime.h>
#include <math.h>

#define B_    2
#define CIN   32
#define COUT  32
#define D_    40
#define E_    3
#define SP    64000
#define YTOT  4096000
#define YT    8
#define SROW  44                  // 44 words = 176B (16B mult); bank mult 12
#define SLABROWS 30
#define SLABVOL (SLABROWS*SROW+4) // 1324 (4 zero pad words for row-29 halo)
#define WV    1152                // 32 oc x stride 36 per ic (tf32 bits)
#define NTHR  160

// k-slot permutation: slot kr -> tap (-1 = zero pad). Quads (kr/4) are bank-spread.
__device__ const int SLOT2TAP[32] = {
     0, 24, 15,  6,   1, 25, 16,  7,   2, 26, 17,  8,
    12,  3, -1, 21,  13,  4, -1, 22,  14,  5, -1, 23,
    18,  9, -1, -1,  19, 10, 20, 11 };
// smem word offset for each k-slot (row*44 + kx for the slot's tap; pads -> zero words)
__device__ const int OFFTAB[32] = {
      0, 968, 528,  88,    1, 969, 529,  89,    2, 970, 530,  90,
    484,  44, 308, 924,  485,  45, 309, 925,  486,  46, 310, 926,
    880, 440,   0, 968,  881, 441, 882, 442 };

// ---- scratch (device globals; no runtime allocation) ----
__device__ unsigned g_wt[B_*CIN*WV];   // [b][ic][oc32 stride36][k-slot] tf32 bits
__device__ float g_bias[B_*COUT];
__device__ float g_y[YTOT];
__device__ float g_sum[COUT];
__device__ float g_sumsq[COUT];

__device__ __forceinline__ void mma_tf32(float* c, const unsigned* a,
                                         unsigned b0, unsigned b1) {
    asm volatile(
        "mma.sync.aligned.m16n8k8.row.col.f32.tf32.tf32.f32 "
        "{%0,%1,%2,%3}, {%4,%5,%6,%7}, {%8,%9}, {%0,%1,%2,%3};\n"
        : "+f"(c[0]), "+f"(c[1]), "+f"(c[2]), "+f"(c[3])
        : "r"(a[0]), "r"(a[1]), "r"(a[2]), "r"(a[3]), "r"(b0), "r"(b1));
}
__device__ __forceinline__ unsigned to_tf32(float f) {
    unsigned u;
    asm("cvt.rna.tf32.f32 %0, %1;" : "=r"(u) : "f"(f));
    return u;
}

// ---------------------------------------------------------------------------
// Kernel 1: routing + combined weights (permuted slots, [oc][k] stride 36)
// ---------------------------------------------------------------------------
__global__ void k_route(const float* __restrict__ emb,
                        const float* __restrict__ rw,
                        const float* __restrict__ rb,
                        const float* __restrict__ ek,
                        const float* __restrict__ eb) {
    float r[B_][E_];
    #pragma unroll
    for (int b = 0; b < B_; b++)
        #pragma unroll
        for (int e = 0; e < E_; e++) {
            float t = fmaf(emb[b], rw[e], rb[e]);
            r[b][e] = 1.0f / (1.0f + expf(-t));
        }

    int idx = blockIdx.x * blockDim.x + threadIdx.x;
    if (idx < B_ * CIN * 1024) {         // 65536: lane = kr (coalesced in k)
        int kr = idx & 31;
        int oc = (idx >> 5) & 31;
        int ic = (idx >> 10) & 31;
        int b  = idx >> 15;
        int tap = SLOT2TAP[kr];
        unsigned u = 0u;
        if (tap >= 0) {
            float s = 0.0f;
            #pragma unroll
            for (int e = 0; e < E_; e++)
                s = fmaf(r[b][e], ek[((e * COUT + oc) * CIN + ic) * 27 + tap], s);
            u = to_tf32(s);
        }
        g_wt[(size_t)(b * CIN + ic) * WV + oc * 36 + kr] = u;
    }
    if (idx < B_ * COUT) {
        int b = idx / COUT, o = idx - b * COUT;
        float s = 0.0f;
        #pragma unroll
        for (int e = 0; e < E_; e++) s = fmaf(r[b][e], eb[e * COUT + o], s);
        g_bias[idx] = s;
    }
    if (idx < COUT) { g_sum[idx] = 0.0f; g_sumsq[idx] = 0.0f; }
}

// ---------------------------------------------------------------------------
// Kernel 2: TF32 warp-MMA implicit conv, conflict-free smem banking.
// Tile 1z x 8y x 40x, all 32 oc. grid = (200 [z*5+yt], 2 b)
// ---------------------------------------------------------------------------
__global__ void __launch_bounds__(NTHR, 3)
k_conv(const float* __restrict__ x) {
    extern __shared__ float dyn[];
    float* sh      = dyn;                              // [2][SLABVOL]
    unsigned* wsh  = (unsigned*)(dyn + 2 * SLABVOL);   // [2][WV]
    float* red     = dyn + 2 * SLABVOL + 2 * WV;       // [320]

    const int z0 = blockIdx.x / 5;
    const int y0 = (blockIdx.x % 5) * YT;
    const int b  = blockIdx.y;
    const int t  = threadIdx.x;
    const int lane = t & 31, w = t >> 5;
    const int g = lane >> 2, tg = lane & 3;

    for (int i = t; i < 2 * SLABVOL + 2 * WV + 320; i += NTHR) dyn[i] = 0.0f;

    // ---- loaders ----
    const float* xb = x + (size_t)(b * CIN) * SP;
    const int lrow = t >> 1, hlf = t & 1;
    const int lz = lrow / 10, ly2 = lrow % 10;
    const int gz = z0 - 1 + lz, gy = y0 - 1 + ly2;
    const bool rowok = (t < 60) && ((unsigned)gz < D_) && ((unsigned)gy < D_);
    const long grow = (long)gz * 1600 + (long)gy * 40 + 20 * hlf;
    const unsigned sdst0 = (unsigned)__cvta_generic_to_shared(sh)
                         + (unsigned)(lrow * (SROW * 4) + 16 + 80 * hlf);
    const unsigned* gwb = g_wt + (size_t)b * CIN * WV;
    const unsigned wdst0 = (unsigned)__cvta_generic_to_shared(wsh);

    auto prefetch = [&](int ic, int buf) {
        if (rowok) {
            const float* src = xb + (size_t)ic * SP + grow;
            unsigned d = sdst0 + (unsigned)buf * (SLABVOL * 4);
            #pragma unroll
            for (int c = 0; c < 5; c++)
                asm volatile("cp.async.cg.shared.global [%0], [%1], 16;"
                             :: "r"(d + c * 16), "l"(src + c * 4));
        }
        const unsigned* sw = gwb + ic * WV;
        unsigned dw = wdst0 + (unsigned)buf * (WV * 4);
        for (int i = t; i < WV / 4; i += NTHR)
            asm volatile("cp.async.cg.shared.global [%0], [%1], 16;"
                         :: "r"(dw + i * 16), "l"(sw + i * 4));
    };

    // ---- per-lane gather offsets from permuted table ----
    int off0[4], off1[4];
    #pragma unroll
    for (int kc = 0; kc < 4; kc++) {
        off0[kc] = OFFTAB[8 * kc + tg];
        off1[kc] = OFFTAB[8 * kc + 4 + tg];
    }
    int cgb[8];
    #pragma unroll
    for (int j = 0; j < 8; j++) {
        int cgg = w * 8 + j;
        cgb[j] = (cgg / 5) * SROW + 3 + (cgg % 5) * 8 + g;
    }

    float C[8][2][4];
    #pragma unroll
    for (int j = 0; j < 8; j++)
        #pragma unroll
        for (int h = 0; h < 2; h++)
            #pragma unroll
            for (int q = 0; q < 4; q++) C[j][h][q] = 0.0f;

    __syncthreads();
    prefetch(0, 0);
    asm volatile("cp.async.commit_group;");

    for (int ic = 0; ic < CIN; ic++) {
        __syncthreads();
        if (ic + 1 < CIN) prefetch(ic + 1, (ic + 1) & 1);
        asm volatile("cp.async.commit_group;");
        asm volatile("cp.async.wait_group 1;");
        __syncthreads();

        const float* S = sh + (ic & 1) * SLABVOL;
        const unsigned* Wm = wsh + (ic & 1) * WV;

        // A frags: [oc][k] stride 36 -> bank = 4g+tg+c, conflict-free
        unsigned A[2][4][4];
        #pragma unroll
        for (int h = 0; h < 2; h++)
            #pragma unroll
            for (int kc = 0; kc < 4; kc++) {
                int base = (16 * h + g) * 36 + 8 * kc + tg;
                A[h][kc][0] = Wm[base];
                A[h][kc][1] = Wm[base + 8 * 36];
                A[h][kc][2] = Wm[base + 4];
                A[h][kc][3] = Wm[base + 8 * 36 + 4];
            }

        #pragma unroll
        for (int j = 0; j < 8; j++) {
            const float* Sj = S + cgb[j];
            #pragma unroll
            for (int kc = 0; kc < 4; kc++) {
                unsigned b0 = to_tf32(Sj[off0[kc]]);
                unsigned b1 = to_tf32(Sj[off1[kc]]);
                mma_tf32(C[j][0], A[0][kc], b0, b1);
                mma_tf32(C[j][1], A[1][kc], b0, b1);
            }
        }
    }

    // ---- epilogue: bias, store y, BN partial sums ----
    float s1[4] = {0.f, 0.f, 0.f, 0.f}, s2[4] = {0.f, 0.f, 0.f, 0.f};
    float bia[4];
    #pragma unroll
    for (int q = 0; q < 4; q++) bia[q] = g_bias[b * COUT + g + 8 * q];

    #pragma unroll
    for (int j = 0; j < 8; j++) {
        int cgg = w * 8 + j;
        size_t sp = (size_t)z0 * 1600 + (size_t)(y0 + cgg / 5) * 40
                  + (cgg % 5) * 8 + 2 * tg;
        #pragma unroll
        for (int h = 0; h < 2; h++) {
            int oclo = g + 16 * h, ochi = oclo + 8;
            float blo = bia[2 * h], bhi = bia[2 * h + 1];
            float v0 = C[j][h][0] + blo, v1 = C[j][h][1] + blo;
            float v2 = C[j][h][2] + bhi, v3 = C[j][h][3] + bhi;
            s1[2*h]   += v0 + v1; s2[2*h]   = fmaf(v0, v0, fmaf(v1, v1, s2[2*h]));
            s1[2*h+1] += v2 + v3; s2[2*h+1] = fmaf(v2, v2, fmaf(v3, v3, s2[2*h+1]));
            *(float2*)(g_y + (size_t)(b * COUT + oclo) * SP + sp) = make_float2(v0, v1);
            *(float2*)(g_y + (size_t)(b * COUT + ochi) * SP + sp) = make_float2(v2, v3);
        }
    }
    #pragma unroll
    for (int q = 0; q < 4; q++) {
        s1[q] += __shfl_down_sync(0xffffffffu, s1[q], 2, 4);
        s1[q] += __shfl_down_sync(0xffffffffu, s1[q], 1, 4);
        s2[q] += __shfl_down_sync(0xffffffffu, s2[q], 2, 4);
        s2[q] += __shfl_down_sync(0xffffffffu, s2[q], 1, 4);
    }
    __syncthreads();
    if (tg == 0) {
        #pragma unroll
        for (int q = 0; q < 4; q++) {
            red[(g + 8 * q) * 5 + w]       = s1[q];
            red[160 + (g + 8 * q) * 5 + w] = s2[q];
        }
    }
    __syncthreads();
    if (t < COUT) {
        float a = 0.0f, qq = 0.0f;
        #pragma unroll
        for (int i = 0; i < 5; i++) { a += red[t * 5 + i]; qq += red[160 + t * 5 + i]; }
        atomicAdd(&g_sum[t], a);
        atomicAdd(&g_sumsq[t], qq);
    }
}

// ---------------------------------------------------------------------------
// Kernel 3: BN finalize + affine + LeakyReLU + nearest upsample x2
// ---------------------------------------------------------------------------
__global__ void __launch_bounds__(256)
k_up(const float* __restrict__ gamma, const float* __restrict__ beta,
     float* __restrict__ out) {
    int idx = blockIdx.x * blockDim.x + threadIdx.x;  // over YTOT/2
    if (idx >= YTOT / 2) return;
    int i2 = idx * 2;
    int xw = i2 % 40;
    int rest = i2 / 40;
    int yw = rest % 40; rest /= 40;
    int zw = rest % 40; rest /= 40;
    int c  = rest % COUT;
    int b  = rest / COUT;

    const float invn = 1.0f / (float)(B_ * SP);
    float mean = g_sum[c] * invn;
    float var  = g_sumsq[c] * invn - mean * mean;
    float sc = gamma[c] * rsqrtf(var + 1e-5f);
    float sf = beta[c] - mean * sc;

    float2 v = *(const float2*)&g_y[i2];
    float a0 = fmaf(sc, v.x, sf); a0 = (a0 >= 0.0f) ? a0 : 0.1f * a0;
    float a1 = fmaf(sc, v.y, sf); a1 = (a1 >= 0.0f) ? a1 : 0.1f * a1;
    float4 p = make_float4(a0, a0, a1, a1);

    size_t base = ((size_t)(b * COUT + c) * 512000u)
                + (size_t)(2 * zw) * 6400u + (size_t)(2 * yw) * 80u + (size_t)(2 * xw);
    float4* o4 = (float4*)(out + base);
    o4[0]    = p;
    o4[20]   = p;
    o4[1600] = p;
    o4[1620] = p;
}

// ---------------------------------------------------------------------------
extern "C" void kernel_launch(void* const* d_in, const int* in_sizes, int n_in,
                              void* d_out, int out_size) {
    const float* x     = (const float*)d_in[0];
    const float* emb   = (const float*)d_in[1];
    const float* rw    = (const float*)d_in[2];
    const float* rb    = (const float*)d_in[3];
    const float* ek    = (const float*)d_in[4];
    const float* eb    = (const float*)d_in[5];
    const float* gamma = (const float*)d_in[6];
    const float* beta  = (const float*)d_in[7];
    float* out = (float*)d_out;

    k_route<<<(B_ * CIN * 1024 + 255) / 256, 256>>>(emb, rw, rb, ek, eb);

    size_t shbytes = (size_t)(2 * SLABVOL + 2 * WV + 320) * sizeof(float);  // ~21 KB
    cudaFuncSetAttribute(k_conv, cudaFuncAttributeMaxDynamicSharedMemorySize, (int)shbytes);
    dim3 gconv(200, B_);
    k_conv<<<gconv, NTHR, shbytes>>>(x);

    k_up<<<(YTOT / 2 + 255) / 256, 256>>>(gamma, beta, out);
}